// round 5
// baseline (speedup 1.0000x reference)
#include <cuda_runtime.h>
#include <cuda_bf16.h>
#include <cstdint>
#include <math.h>

#define LN   2048
#define BN_  4
#define EN   1024
#define HN   8
#define D1N  2048
#define HDN  256
#define MN   (LN*BN_)   // 8192

// ---------------- device scratch ----------------
__device__ __align__(16) __nv_bfloat16 g_xh[MN*EN],  g_xl[MN*EN];
__device__ __align__(16) __nv_bfloat16 g_uwh[D1N*EN], g_uwl[D1N*EN];
__device__ __align__(16) __nv_bfloat16 g_vwh[D1N*EN], g_vwl[D1N*EN];
__device__ __align__(16) __nv_bfloat16 g_owh[EN*D1N], g_owl[EN*D1N];
__device__ __align__(16) float g_u[MN*D1N];
__device__ __align__(16) float g_v[MN*D1N];
__device__ __align__(16) __nv_bfloat16 g_vth[(size_t)32*HDN*LN], g_vtl[(size_t)32*HDN*LN];
__device__ __align__(16) __nv_bfloat16 g_ah[MN*D1N], g_al[MN*D1N];
__device__ __align__(16) __nv_bfloat16 g_th[HN*4096], g_tl[HN*4096];
// precomputed toeplitz A tiles: 8 heads x 62 deltas x (128x64) bf16, pre-swizzled
__device__ __align__(16) __nv_bfloat16 g_tth[(size_t)HN*62*8192], g_ttl[(size_t)HN*62*8192];

// ---------------- helpers ----------------
__device__ __forceinline__ uint32_t smem_u32(const void* p){
    uint32_t a;
    asm("{ .reg .u64 t; cvta.to.shared.u64 t, %1; cvt.u32.u64 %0, t; }" : "=r"(a) : "l"(p));
    return a;
}
#define SWZ(o) ((uint32_t)(o) ^ ((((uint32_t)(o))>>3)&0x70))

__device__ __forceinline__ uint32_t pk(float a, float b){
    __nv_bfloat16 x = __float2bfloat16(a), y = __float2bfloat16(b);
    return (uint32_t)__bfloat16_as_ushort(x) | ((uint32_t)__bfloat16_as_ushort(y)<<16);
}
__device__ __forceinline__ void ldsm4(uint32_t* r, uint32_t addr){
    asm volatile("ldmatrix.sync.aligned.m8n8.x4.shared.b16 {%0,%1,%2,%3}, [%4];"
                 : "=r"(r[0]),"=r"(r[1]),"=r"(r[2]),"=r"(r[3]) : "r"(addr));
}
__device__ __forceinline__ void ldsm2(uint32_t* r, uint32_t addr){
    asm volatile("ldmatrix.sync.aligned.m8n8.x2.shared.b16 {%0,%1}, [%2];"
                 : "=r"(r[0]),"=r"(r[1]) : "r"(addr));
}
__device__ __forceinline__ void mma16816(float* d, const uint32_t* a, const uint32_t* b){
    asm volatile("mma.sync.aligned.m16n8k16.row.col.f32.bf16.bf16.f32 "
        "{%0,%1,%2,%3}, {%4,%5,%6,%7}, {%8,%9}, {%0,%1,%2,%3};"
        : "+f"(d[0]),"+f"(d[1]),"+f"(d[2]),"+f"(d[3])
        : "r"(a[0]),"r"(a[1]),"r"(a[2]),"r"(a[3]), "r"(b[0]),"r"(b[1]));
}
__device__ __forceinline__ void cpa16(uint32_t s, const void* g){
    asm volatile("cp.async.cg.shared.global [%0], [%1], 16;" :: "r"(s), "l"(g));
}
__device__ __forceinline__ void cpa_commit(){ asm volatile("cp.async.commit_group;" ::: "memory"); }
__device__ __forceinline__ void cpa_wait0(){ asm volatile("cp.async.wait_group 0;" ::: "memory"); }
__device__ __forceinline__ void cpa_wait1(){ asm volatile("cp.async.wait_group 1;" ::: "memory"); }

// SMEM per stage: A_hi 32K (256x64) | A_lo 32K | B_hi 16K (128x64) | B_lo 16K
#define TA_H 0
#define TA_L 32768
#define TB_H 65536
#define TB_L 81920
#define STG  98304
#define SMEM_SZ (2*STG)   // 196608

// ---------------------------------------------------------------------------
__global__ void rmsnorm_k(const float* __restrict__ q,
                          __nv_bfloat16* __restrict__ xh, __nv_bfloat16* __restrict__ xl)
{
    int m = blockIdx.x, t = threadIdx.x;
    float4 a = reinterpret_cast<const float4*>(q + (size_t)m*EN)[t];
    float ss = a.x*a.x + a.y*a.y + a.z*a.z + a.w*a.w;
    #pragma unroll
    for (int o=16;o;o>>=1) ss += __shfl_xor_sync(0xffffffffu, ss, o);
    __shared__ float sred[8];
    if ((t&31)==0) sred[t>>5] = ss;
    __syncthreads();
    if (t<8){
        float v = sred[t];
        #pragma unroll
        for (int o=4;o;o>>=1) v += __shfl_xor_sync(0xffu, v, o);
        if (t==0) sred[0] = v;
    }
    __syncthreads();
    float inv = 1.0f / (sqrtf(sred[0]*(1.0f/EN)) + 1e-8f);
    float v0=a.x*inv, v1=a.y*inv, v2=a.z*inv, v3=a.w*inv;
    __nv_bfloat16 h0=__float2bfloat16(v0), h1=__float2bfloat16(v1),
                  h2=__float2bfloat16(v2), h3=__float2bfloat16(v3);
    size_t off = (size_t)m*EN + t*4;
    uint2 wh = make_uint2(
        (uint32_t)__bfloat16_as_ushort(h0) | ((uint32_t)__bfloat16_as_ushort(h1)<<16),
        (uint32_t)__bfloat16_as_ushort(h2) | ((uint32_t)__bfloat16_as_ushort(h3)<<16));
    uint2 wl = make_uint2(
        pk(v0-__bfloat162float(h0), v1-__bfloat162float(h1)),
        pk(v2-__bfloat162float(h2), v3-__bfloat162float(h3)));
    *reinterpret_cast<uint2*>(xh+off) = wh;
    *reinterpret_cast<uint2*>(xl+off) = wl;
}

__global__ void split_k(const float* __restrict__ w,
                        __nv_bfloat16* __restrict__ oh, __nv_bfloat16* __restrict__ ol, int n4)
{
    int i = blockIdx.x*256 + threadIdx.x;
    if (i >= n4) return;
    float4 a = reinterpret_cast<const float4*>(w)[i];
    __nv_bfloat16 h0=__float2bfloat16(a.x), h1=__float2bfloat16(a.y),
                  h2=__float2bfloat16(a.z), h3=__float2bfloat16(a.w);
    uint2 wh = make_uint2(
        (uint32_t)__bfloat16_as_ushort(h0) | ((uint32_t)__bfloat16_as_ushort(h1)<<16),
        (uint32_t)__bfloat16_as_ushort(h2) | ((uint32_t)__bfloat16_as_ushort(h3)<<16));
    uint2 wl = make_uint2(
        pk(a.x-__bfloat162float(h0), a.y-__bfloat162float(h1)),
        pk(a.z-__bfloat162float(h2), a.w-__bfloat162float(h3)));
    reinterpret_cast<uint2*>(oh)[i] = wh;
    reinterpret_cast<uint2*>(ol)[i] = wl;
}

__global__ void build_t_k(const float* __restrict__ pos, const float* __restrict__ zero,
                          const float* __restrict__ neg)
{
    int h = blockIdx.y;
    int k = blockIdx.x*256 + threadIdx.x;
    if (k >= LN) return;
    int base = h*4096;
    auto wr = [&](int idx, float v){
        __nv_bfloat16 hi = __float2bfloat16(v);
        g_th[base+idx] = hi;
        g_tl[base+idx] = __float2bfloat16(v - __bfloat162float(hi));
    };
    if (k==0){ wr(2047, zero[h]); wr(4095, 0.f); }
    else { wr(2047+k, pos[h*(LN-1)+k-1]); wr(2047-k, neg[h*(LN-1)+k-1]); }
}

// ---------------------------------------------------------------------------
// Precompute toeplitz A tiles (128x64, SW128-swizzled)
// ---------------------------------------------------------------------------
__global__ void toeptiles_k()
{
    __shared__ uint16_t sH[192], sL[192];
    int ti = blockIdx.x, h = blockIdx.y, tid = threadIdx.x;
    int gb = h*4096 + 1984 + (ti-31)*64;
    if (tid < 191){
        sH[tid] = ((const uint16_t*)g_th)[gb+tid];
        sL[tid] = ((const uint16_t*)g_tl)[gb+tid];
    }
    __syncthreads();
    size_t tb = ((size_t)h*62 + ti)*8192;
    char* dh = (char*)g_tth + tb*2;
    char* dl = (char*)g_ttl + tb*2;
    #pragma unroll
    for (int it=0;it<4;it++){
        int idx = it*256+tid, m = idx>>3, k8 = (idx&7)<<3;
        int base = m + 63 - k8;
        uint32_t so = SWZ(m*128 + k8*2);
        uint32_t w0 = (uint32_t)sH[base]   | ((uint32_t)sH[base-1]<<16);
        uint32_t w1 = (uint32_t)sH[base-2] | ((uint32_t)sH[base-3]<<16);
        uint32_t w2 = (uint32_t)sH[base-4] | ((uint32_t)sH[base-5]<<16);
        uint32_t w3 = (uint32_t)sH[base-6] | ((uint32_t)sH[base-7]<<16);
        *(uint4*)(dh+so) = make_uint4(w0,w1,w2,w3);
        w0 = (uint32_t)sL[base]   | ((uint32_t)sL[base-1]<<16);
        w1 = (uint32_t)sL[base-2] | ((uint32_t)sL[base-3]<<16);
        w2 = (uint32_t)sL[base-4] | ((uint32_t)sL[base-5]<<16);
        w3 = (uint32_t)sL[base-6] | ((uint32_t)sL[base-7]<<16);
        *(uint4*)(dl+so) = make_uint4(w0,w1,w2,w3);
    }
}

// ---------------------------------------------------------------------------
// MMA core: 16 warps cover 256x128 tile; per warp 64x32, 3-segment split.
// ---------------------------------------------------------------------------
struct Acc { float a[4][4][4]; };

__device__ __forceinline__ void mma_stage(Acc& A, uint32_t base, int wm0, int wn0, int lid)
{
    #pragma unroll
    for (int ks=0;ks<4;ks++){
        uint32_t ahf[4][4], alf[4][4], bhf[4][2], blf[4][2];
        int arow = ((lid>>3)&1)*8 + (lid&7);
        int acol = ks*16 + ((lid>>4)&1)*8;
        #pragma unroll
        for (int mi=0;mi<4;mi++){
            uint32_t off = SWZ((wm0+mi*16+arow)*128 + acol*2);
            ldsm4(ahf[mi], base+TA_H+off);
            ldsm4(alf[mi], base+TA_L+off);
        }
        int l2 = lid&15;
        int brow = l2&7;
        int bcol = ks*16 + ((l2>>3)&1)*8;
        #pragma unroll
        for (int ni=0;ni<4;ni++){
            uint32_t off = SWZ((wn0+ni*8+brow)*128 + bcol*2);
            ldsm2(bhf[ni], base+TB_H+off);
            ldsm2(blf[ni], base+TB_L+off);
        }
        #pragma unroll
        for (int mi=0;mi<4;mi++)
            #pragma unroll
            for (int ni=0;ni<4;ni++){
                mma16816(A.a[mi][ni], ahf[mi], bhf[ni]);
                mma16816(A.a[mi][ni], ahf[mi], blf[ni]);
                mma16816(A.a[mi][ni], alf[mi], bhf[ni]);
            }
    }
}

// ---------------------------------------------------------------------------
// Pipelined split-bf16 GEMM, tile 256x128, K-chunk 64, 2-stage cp.async.
// ---------------------------------------------------------------------------
template<int EPI>
__global__ void __launch_bounds__(512, 1)
gemm_k(const __nv_bfloat16* __restrict__ Ah, const __nv_bfloat16* __restrict__ Al,
       const __nv_bfloat16* __restrict__ Bh, const __nv_bfloat16* __restrict__ Bl,
       const float* __restrict__ bias, const float* __restrict__ resid,
       float* __restrict__ C, int K, int Nld)
{
    extern __shared__ char smem[];
    const uint32_t sb = smem_u32(smem);
    int tid = threadIdx.x, wid = tid>>5, lid = tid&31;
    int i0 = blockIdx.y*256, n0 = blockIdx.x*128;
    int wm0 = (wid>>2)*64, wn0 = (wid&3)*32;
    Acc acc;
    #pragma unroll
    for (int i=0;i<4;i++)
        #pragma unroll
        for (int j=0;j<4;j++)
            #pragma unroll
            for (int r=0;r<4;r++) acc.a[i][j][r] = 0.f;

    int lr = tid>>3, lq = tid&7;                 // 512 thr -> 64 rows x 8 col-chunks
    uint32_t soT = SWZ(lr*128 + lq*16);

    auto load_chunk = [&](int c, int st){
        uint32_t bs = sb + st*STG;
        int kt = c<<6;
        #pragma unroll
        for (int it=0;it<4;it++){               // A: 256 rows
            int r = lr + it*64;
            uint32_t so = soT + it*8192;
            size_t goA = (size_t)(i0 + r)*K + kt + lq*8;
            cpa16(bs+TA_H+so, Ah+goA);
            cpa16(bs+TA_L+so, Al+goA);
        }
        #pragma unroll
        for (int it=0;it<2;it++){               // B: 128 rows
            int r = lr + it*64;
            uint32_t so = soT + it*8192;
            size_t goB = (size_t)(n0 + r)*K + kt + lq*8;
            cpa16(bs+TB_H+so, Bh+goB);
            cpa16(bs+TB_L+so, Bl+goB);
        }
        cpa_commit();
    };

    const int nch = K>>6;
    load_chunk(0, 0);
    for (int c=0;c<nch;c++){
        if (c+1 < nch){ load_chunk(c+1, (c+1)&1); cpa_wait1(); }
        else          { cpa_wait0(); }
        __syncthreads();
        mma_stage(acc, sb + (c&1)*STG, wm0, wn0, lid);
        __syncthreads();
    }

    #pragma unroll
    for (int mi=0;mi<4;mi++)
        #pragma unroll
        for (int ni=0;ni<4;ni++){
            int nn = n0 + wn0 + ni*8 + 2*(lid&3);
            #pragma unroll
            for (int half=0;half<2;half++){
                int m = i0 + wm0 + mi*16 + (lid>>2) + half*8;
                float v0 = acc.a[mi][ni][2*half+0], v1 = acc.a[mi][ni][2*half+1];
                float o0, o1;
                if (EPI==0){
                    float s0 = v0 + bias[nn], s1 = v1 + bias[nn+1];
                    o0 = s0 / (1.0f + __expf(-s0)); o1 = s1 / (1.0f + __expf(-s1));
                } else {
                    const float* rp = resid + (size_t)m*Nld + nn;
                    o0 = v0 + bias[nn] + rp[0]; o1 = v1 + bias[nn+1] + rp[1];
                }
                *(float2*)(C + (size_t)m*Nld + nn) = make_float2(o0, o1);
            }
        }
}

// ---------------------------------------------------------------------------
// transpose + split v
// ---------------------------------------------------------------------------
__global__ void transsplit_k(const float* __restrict__ V,
                             __nv_bfloat16* __restrict__ Oh, __nv_bfloat16* __restrict__ Ol)
{
    __shared__ float t[32][33];
    int s = blockIdx.z, h = s>>2, b = s&3;
    int j0 = blockIdx.x*32, d0 = blockIdx.y*32;
    int tx = threadIdx.x, ty = threadIdx.y;
    #pragma unroll
    for (int r=0;r<4;r++){
        int j = j0 + ty + r*8;
        t[ty+r*8][tx] = V[((size_t)j*BN_ + b)*D1N + h*HDN + d0 + tx];
    }
    __syncthreads();
    #pragma unroll
    for (int r=0;r<4;r++){
        int d = d0 + ty + r*8;
        float v = t[tx][ty+r*8];
        __nv_bfloat16 hi = __float2bfloat16(v);
        size_t off = ((size_t)s*HDN + d)*LN + j0 + tx;
        Oh[off] = hi;
        Ol[off] = __float2bfloat16(v - __bfloat162float(hi));
    }
}

// ---------------------------------------------------------------------------
// Pipelined toeplitz GEMM: tile 256(l) x 128(d), A = two precomputed tiles.
// ---------------------------------------------------------------------------
__global__ void __launch_bounds__(512, 1)
toep_k(const __nv_bfloat16* __restrict__ Vh_, const __nv_bfloat16* __restrict__ Vl_,
       const float* __restrict__ U,
       __nv_bfloat16* __restrict__ Aoh, __nv_bfloat16* __restrict__ Aol)
{
    extern __shared__ char smem[];
    const uint32_t sb = smem_u32(smem);
    int tid = threadIdx.x, wid = tid>>5, lid = tid&31;
    int s = blockIdx.z, h = s>>2, b = s&3;
    int i0 = blockIdx.y*256;
    int d0 = blockIdx.x*128;
    int wm0 = (wid>>2)*64, wn0 = (wid&3)*32;
    const __nv_bfloat16* vh = Vh_ + (size_t)s*HDN*LN + (size_t)d0*LN;
    const __nv_bfloat16* vl = Vl_ + (size_t)s*HDN*LN + (size_t)d0*LN;
    Acc acc;
    #pragma unroll
    for (int i=0;i<4;i++)
        #pragma unroll
        for (int j=0;j<4;j++)
            #pragma unroll
            for (int r=0;r<4;r++) acc.a[i][j][r] = 0.f;

    int lr = tid>>3, lq = tid&7;
    uint32_t soT = SWZ(lr*128 + lq*16);
    int tibase = blockIdx.y*4 + 31;           // ti0 = tibase - c  (delta = i0 - j0)

    auto load_chunk = [&](int c, int st){
        uint32_t bs = sb + st*STG;
        int j0 = c<<6;
        size_t tbytes = (((size_t)h*62 + (tibase - c))*8192)*2;
        const char* th = (const char*)g_tth + tbytes;
        const char* tl = (const char*)g_ttl + tbytes;
        #pragma unroll
        for (int it=0;it<4;it++){             // A: verbatim copy of two 16KB tiles
            uint32_t lin = (uint32_t)(it*512 + tid)*16;
            uint32_t src = lin + ((lin>>14)<<14);   // second half jumps one tile (+2 in ti)
            cpa16(bs+TA_H+lin, th+src);
            cpa16(bs+TA_L+lin, tl+src);
        }
        #pragma unroll
        for (int it=0;it<2;it++){             // B: 128 d-rows x 64 j
            int r = lr + it*64;
            uint32_t so = soT + it*8192;
            size_t go = (size_t)r*LN + j0 + lq*8;
            cpa16(bs+TB_H+so, vh+go);
            cpa16(bs+TB_L+so, vl+go);
        }
        cpa_commit();
    };

    load_chunk(0, 0);
    for (int c=0;c<32;c++){
        if (c+1 < 32){ load_chunk(c+1, (c+1)&1); cpa_wait1(); }
        else         { cpa_wait0(); }
        __syncthreads();
        mma_stage(acc, sb + (c&1)*STG, wm0, wn0, lid);
        __syncthreads();
    }

    #pragma unroll
    for (int mi=0;mi<4;mi++)
        #pragma unroll
        for (int ni=0;ni<4;ni++){
            int d = d0 + wn0 + ni*8 + 2*(lid&3);
            #pragma unroll
            for (int half=0;half<2;half++){
                int m = i0 + wm0 + mi*16 + (lid>>2) + half*8;
                size_t off = ((size_t)m*BN_ + b)*D1N + h*HDN + d;
                float a0 = acc.a[mi][ni][2*half+0] * U[off];
                float a1 = acc.a[mi][ni][2*half+1] * U[off+1];
                __nv_bfloat16 h0 = __float2bfloat16(a0), h1 = __float2bfloat16(a1);
                *(uint32_t*)(Aoh + off) =
                    (uint32_t)__bfloat16_as_ushort(h0) | ((uint32_t)__bfloat16_as_ushort(h1)<<16);
                *(uint32_t*)(Aol + off) = pk(a0-__bfloat162float(h0), a1-__bfloat162float(h1));
            }
        }
}

// ---------------------------------------------------------------------------
extern "C" void kernel_launch(void* const* d_in, const int* in_sizes, int n_in,
                              void* d_out, int out_size)
{
    const float* q   = (const float*)d_in[0];
    const float* u_w = (const float*)d_in[3];
    const float* u_b = (const float*)d_in[4];
    const float* v_w = (const float*)d_in[5];
    const float* v_b = (const float*)d_in[6];
    const float* o_w = (const float*)d_in[7];
    const float* o_b = (const float*)d_in[8];
    const float* pos = (const float*)d_in[9];
    const float* zer = (const float*)d_in[10];
    const float* neg = (const float*)d_in[11];
    float* out = (float*)d_out;

    cudaFuncSetAttribute(gemm_k<0>, cudaFuncAttributeMaxDynamicSharedMemorySize, SMEM_SZ);
    cudaFuncSetAttribute(gemm_k<1>, cudaFuncAttributeMaxDynamicSharedMemorySize, SMEM_SZ);
    cudaFuncSetAttribute(toep_k,    cudaFuncAttributeMaxDynamicSharedMemorySize, SMEM_SZ);

    void *p;
    #define SYM(v, sym) cudaGetSymbolAddress(&p, sym); auto* v = (decltype(&sym[0]))p;
    SYM(xh,  g_xh);  SYM(xl,  g_xl);
    SYM(uwh, g_uwh); SYM(uwl, g_uwl);
    SYM(vwh, g_vwh); SYM(vwl, g_vwl);
    SYM(owh, g_owh); SYM(owl, g_owl);
    SYM(ug,  g_u);   SYM(vg,  g_v);
    SYM(vth, g_vth); SYM(vtl, g_vtl);
    SYM(ah,  g_ah);  SYM(al,  g_al);
    #undef SYM

    rmsnorm_k<<<MN, 256>>>(q, xh, xl);
    split_k<<<(D1N*EN/4+255)/256, 256>>>(u_w, uwh, uwl, D1N*EN/4);
    split_k<<<(D1N*EN/4+255)/256, 256>>>(v_w, vwh, vwl, D1N*EN/4);
    split_k<<<(EN*D1N/4+255)/256, 256>>>(o_w, owh, owl, EN*D1N/4);
    build_t_k<<<dim3(LN/256, HN), 256>>>(pos, zer, neg);
    toeptiles_k<<<dim3(62, HN), 256>>>();
    gemm_k<0><<<dim3(D1N/128, MN/256), 512, SMEM_SZ>>>(xh, xl, uwh, uwl, u_b, nullptr, ug, EN, D1N);
    gemm_k<0><<<dim3(D1N/128, MN/256), 512, SMEM_SZ>>>(xh, xl, vwh, vwl, v_b, nullptr, vg, EN, D1N);
    transsplit_k<<<dim3(LN/32, HDN/32, 32), dim3(32,8)>>>(vg, vth, vtl);
    toep_k<<<dim3(HDN/128, LN/256, 32), 512, SMEM_SZ>>>(vth, vtl, ug, ah, al);
    gemm_k<1><<<dim3(EN/128, MN/256), 512, SMEM_SZ>>>(ah, al, owh, owl, o_b, q, out, D1N, EN);
}

// round 6
// speedup vs baseline: 1.1223x; 1.1223x over previous
#include <cuda_runtime.h>
#include <cuda_bf16.h>
#include <cstdint>
#include <math.h>

#define LN   2048
#define BN_  4
#define EN   1024
#define HN   8
#define D1N  2048
#define HDN  256
#define MN   (LN*BN_)   // 8192

// ---------------- device scratch ----------------
__device__ __align__(16) __nv_bfloat16 g_xh[MN*EN],  g_xl[MN*EN];
__device__ __align__(16) __nv_bfloat16 g_uwh[D1N*EN], g_uwl[D1N*EN];
__device__ __align__(16) __nv_bfloat16 g_vwh[D1N*EN], g_vwl[D1N*EN];
__device__ __align__(16) __nv_bfloat16 g_owh[EN*D1N], g_owl[EN*D1N];
__device__ __align__(16) float g_u[MN*D1N];
__device__ __align__(16) float g_v[MN*D1N];
__device__ __align__(16) __nv_bfloat16 g_vth[(size_t)32*HDN*LN], g_vtl[(size_t)32*HDN*LN];
__device__ __align__(16) __nv_bfloat16 g_ah[MN*D1N], g_al[MN*D1N];
__device__ __align__(16) __nv_bfloat16 g_th[HN*4096], g_tl[HN*4096];
// precomputed toeplitz A tiles: 8 heads x 62 deltas x (128x64) bf16, pre-swizzled
__device__ __align__(16) __nv_bfloat16 g_tth[(size_t)HN*62*8192], g_ttl[(size_t)HN*62*8192];

// ---------------- helpers ----------------
__device__ __forceinline__ uint32_t smem_u32(const void* p){
    uint32_t a;
    asm("{ .reg .u64 t; cvta.to.shared.u64 t, %1; cvt.u32.u64 %0, t; }" : "=r"(a) : "l"(p));
    return a;
}
#define SWZ(o) ((uint32_t)(o) ^ ((((uint32_t)(o))>>3)&0x70))

__device__ __forceinline__ uint32_t pk(float a, float b){
    __nv_bfloat16 x = __float2bfloat16(a), y = __float2bfloat16(b);
    return (uint32_t)__bfloat16_as_ushort(x) | ((uint32_t)__bfloat16_as_ushort(y)<<16);
}
__device__ __forceinline__ void ldsm4(uint32_t* r, uint32_t addr){
    asm volatile("ldmatrix.sync.aligned.m8n8.x4.shared.b16 {%0,%1,%2,%3}, [%4];"
                 : "=r"(r[0]),"=r"(r[1]),"=r"(r[2]),"=r"(r[3]) : "r"(addr));
}
__device__ __forceinline__ void ldsm2(uint32_t* r, uint32_t addr){
    asm volatile("ldmatrix.sync.aligned.m8n8.x2.shared.b16 {%0,%1}, [%2];"
                 : "=r"(r[0]),"=r"(r[1]) : "r"(addr));
}
__device__ __forceinline__ void mma16816(float* d, const uint32_t* a, const uint32_t* b){
    asm volatile("mma.sync.aligned.m16n8k16.row.col.f32.bf16.bf16.f32 "
        "{%0,%1,%2,%3}, {%4,%5,%6,%7}, {%8,%9}, {%0,%1,%2,%3};"
        : "+f"(d[0]),"+f"(d[1]),"+f"(d[2]),"+f"(d[3])
        : "r"(a[0]),"r"(a[1]),"r"(a[2]),"r"(a[3]), "r"(b[0]),"r"(b[1]));
}
__device__ __forceinline__ void cpa16(uint32_t s, const void* g){
    asm volatile("cp.async.cg.shared.global [%0], [%1], 16;" :: "r"(s), "l"(g));
}
__device__ __forceinline__ void cpa_commit(){ asm volatile("cp.async.commit_group;" ::: "memory"); }
__device__ __forceinline__ void cpa_wait0(){ asm volatile("cp.async.wait_group 0;" ::: "memory"); }
__device__ __forceinline__ void cpa_wait1(){ asm volatile("cp.async.wait_group 1;" ::: "memory"); }

// SMEM per stage: A_hi 16K | A_lo 16K | B_hi 16K | B_lo 16K  (128x64 bf16 each)
#define TA_H 0
#define TA_L 16384
#define TB_H 32768
#define TB_L 49152
#define STG  65536
#define SMEM_SZ (3*STG)   // 196608, 3-stage pipeline

// ---------------------------------------------------------------------------
__global__ void rmsnorm_k(const float* __restrict__ q,
                          __nv_bfloat16* __restrict__ xh, __nv_bfloat16* __restrict__ xl)
{
    int m = blockIdx.x, t = threadIdx.x;
    float4 a = reinterpret_cast<const float4*>(q + (size_t)m*EN)[t];
    float ss = a.x*a.x + a.y*a.y + a.z*a.z + a.w*a.w;
    #pragma unroll
    for (int o=16;o;o>>=1) ss += __shfl_xor_sync(0xffffffffu, ss, o);
    __shared__ float sred[8];
    if ((t&31)==0) sred[t>>5] = ss;
    __syncthreads();
    if (t<8){
        float v = sred[t];
        #pragma unroll
        for (int o=4;o;o>>=1) v += __shfl_xor_sync(0xffu, v, o);
        if (t==0) sred[0] = v;
    }
    __syncthreads();
    float inv = 1.0f / (sqrtf(sred[0]*(1.0f/EN)) + 1e-8f);
    float v0=a.x*inv, v1=a.y*inv, v2=a.z*inv, v3=a.w*inv;
    __nv_bfloat16 h0=__float2bfloat16(v0), h1=__float2bfloat16(v1),
                  h2=__float2bfloat16(v2), h3=__float2bfloat16(v3);
    size_t off = (size_t)m*EN + t*4;
    uint2 wh = make_uint2(
        (uint32_t)__bfloat16_as_ushort(h0) | ((uint32_t)__bfloat16_as_ushort(h1)<<16),
        (uint32_t)__bfloat16_as_ushort(h2) | ((uint32_t)__bfloat16_as_ushort(h3)<<16));
    uint2 wl = make_uint2(
        pk(v0-__bfloat162float(h0), v1-__bfloat162float(h1)),
        pk(v2-__bfloat162float(h2), v3-__bfloat162float(h3)));
    *reinterpret_cast<uint2*>(xh+off) = wh;
    *reinterpret_cast<uint2*>(xl+off) = wl;
}

__global__ void split_k(const float* __restrict__ w,
                        __nv_bfloat16* __restrict__ oh, __nv_bfloat16* __restrict__ ol, int n4)
{
    int i = blockIdx.x*256 + threadIdx.x;
    if (i >= n4) return;
    float4 a = reinterpret_cast<const float4*>(w)[i];
    __nv_bfloat16 h0=__float2bfloat16(a.x), h1=__float2bfloat16(a.y),
                  h2=__float2bfloat16(a.z), h3=__float2bfloat16(a.w);
    uint2 wh = make_uint2(
        (uint32_t)__bfloat16_as_ushort(h0) | ((uint32_t)__bfloat16_as_ushort(h1)<<16),
        (uint32_t)__bfloat16_as_ushort(h2) | ((uint32_t)__bfloat16_as_ushort(h3)<<16));
    uint2 wl = make_uint2(
        pk(a.x-__bfloat162float(h0), a.y-__bfloat162float(h1)),
        pk(a.z-__bfloat162float(h2), a.w-__bfloat162float(h3)));
    reinterpret_cast<uint2*>(oh)[i] = wh;
    reinterpret_cast<uint2*>(ol)[i] = wl;
}

__global__ void build_t_k(const float* __restrict__ pos, const float* __restrict__ zero,
                          const float* __restrict__ neg)
{
    int h = blockIdx.y;
    int k = blockIdx.x*256 + threadIdx.x;
    if (k >= LN) return;
    int base = h*4096;
    auto wr = [&](int idx, float v){
        __nv_bfloat16 hi = __float2bfloat16(v);
        g_th[base+idx] = hi;
        g_tl[base+idx] = __float2bfloat16(v - __bfloat162float(hi));
    };
    if (k==0){ wr(2047, zero[h]); wr(4095, 0.f); }
    else { wr(2047+k, pos[h*(LN-1)+k-1]); wr(2047-k, neg[h*(LN-1)+k-1]); }
}

// ---------------------------------------------------------------------------
// Precompute toeplitz A tiles (128x64, SW128-swizzled)
// ---------------------------------------------------------------------------
__global__ void toeptiles_k()
{
    __shared__ uint16_t sH[192], sL[192];
    int ti = blockIdx.x, h = blockIdx.y, tid = threadIdx.x;
    int gb = h*4096 + 1984 + (ti-31)*64;
    if (tid < 191){
        sH[tid] = ((const uint16_t*)g_th)[gb+tid];
        sL[tid] = ((const uint16_t*)g_tl)[gb+tid];
    }
    __syncthreads();
    size_t tb = ((size_t)h*62 + ti)*8192;
    char* dh = (char*)g_tth + tb*2;
    char* dl = (char*)g_ttl + tb*2;
    #pragma unroll
    for (int it=0;it<4;it++){
        int idx = it*256+tid, m = idx>>3, k8 = (idx&7)<<3;
        int base = m + 63 - k8;
        uint32_t so = SWZ(m*128 + k8*2);
        uint32_t w0 = (uint32_t)sH[base]   | ((uint32_t)sH[base-1]<<16);
        uint32_t w1 = (uint32_t)sH[base-2] | ((uint32_t)sH[base-3]<<16);
        uint32_t w2 = (uint32_t)sH[base-4] | ((uint32_t)sH[base-5]<<16);
        uint32_t w3 = (uint32_t)sH[base-6] | ((uint32_t)sH[base-7]<<16);
        *(uint4*)(dh+so) = make_uint4(w0,w1,w2,w3);
        w0 = (uint32_t)sL[base]   | ((uint32_t)sL[base-1]<<16);
        w1 = (uint32_t)sL[base-2] | ((uint32_t)sL[base-3]<<16);
        w2 = (uint32_t)sL[base-4] | ((uint32_t)sL[base-5]<<16);
        w3 = (uint32_t)sL[base-6] | ((uint32_t)sL[base-7]<<16);
        *(uint4*)(dl+so) = make_uint4(w0,w1,w2,w3);
    }
}

// ---------------------------------------------------------------------------
// MMA core for a 128x128 tile on one staged buffer (3-segment split).
// ---------------------------------------------------------------------------
struct Acc { float a[4][4][4]; };

__device__ __forceinline__ void mma_stage(Acc& A, uint32_t base, int wm0, int wn0, int lid)
{
    #pragma unroll
    for (int ks=0;ks<4;ks++){
        uint32_t ahf[4][4], alf[4][4], bhf[4][2], blf[4][2];
        int arow = ((lid>>3)&1)*8 + (lid&7);
        int acol = ks*16 + ((lid>>4)&1)*8;
        #pragma unroll
        for (int mi=0;mi<4;mi++){
            uint32_t off = SWZ((wm0+mi*16+arow)*128 + acol*2);
            ldsm4(ahf[mi], base+TA_H+off);
            ldsm4(alf[mi], base+TA_L+off);
        }
        int l2 = lid&15;
        int brow = l2&7;
        int bcol = ks*16 + ((l2>>3)&1)*8;
        #pragma unroll
        for (int ni=0;ni<4;ni++){
            uint32_t off = SWZ((wn0+ni*8+brow)*128 + bcol*2);
            ldsm2(bhf[ni], base+TB_H+off);
            ldsm2(blf[ni], base+TB_L+off);
        }
        #pragma unroll
        for (int mi=0;mi<4;mi++)
            #pragma unroll
            for (int ni=0;ni<4;ni++){
                mma16816(A.a[mi][ni], ahf[mi], bhf[ni]);
                mma16816(A.a[mi][ni], ahf[mi], blf[ni]);
                mma16816(A.a[mi][ni], alf[mi], bhf[ni]);
            }
    }
}

// ---------------------------------------------------------------------------
// Pipelined split-bf16 GEMM, tile 128x128, K-chunk 64, 3-stage cp.async,
// single barrier per chunk.
// ---------------------------------------------------------------------------
template<int EPI>
__global__ void __launch_bounds__(256)
gemm_k(const __nv_bfloat16* __restrict__ Ah, const __nv_bfloat16* __restrict__ Al,
       const __nv_bfloat16* __restrict__ Bh, const __nv_bfloat16* __restrict__ Bl,
       const float* __restrict__ bias, const float* __restrict__ resid,
       float* __restrict__ C, int K, int Nld)
{
    extern __shared__ char smem[];
    const uint32_t sb = smem_u32(smem);
    int tid = threadIdx.x, wid = tid>>5, lid = tid&31;
    int i0 = blockIdx.y*128, n0 = blockIdx.x*128;
    int wm0 = (wid>>2)*64, wn0 = (wid&3)*32;
    Acc acc;
    #pragma unroll
    for (int i=0;i<4;i++)
        #pragma unroll
        for (int j=0;j<4;j++)
            #pragma unroll
            for (int r=0;r<4;r++) acc.a[i][j][r] = 0.f;

    int lr = tid>>3, lq = tid&7;                 // 256 thr -> 32 rows x 8 chunks per pass
    uint32_t soT = SWZ(lr*128 + lq*16);

    auto load_chunk = [&](int c, int st){
        uint32_t bs = sb + st*STG;
        int kt = c<<6;
        #pragma unroll
        for (int it=0;it<4;it++){
            int r = lr + it*32;
            uint32_t so = soT + it*(32*128);
            size_t goA = (size_t)(i0 + r)*K + kt + lq*8;
            size_t goB = (size_t)(n0 + r)*K + kt + lq*8;
            cpa16(bs+TA_H+so, Ah+goA);
            cpa16(bs+TA_L+so, Al+goA);
            cpa16(bs+TB_H+so, Bh+goB);
            cpa16(bs+TB_L+so, Bl+goB);
        }
        cpa_commit();
    };

    const int nch = K>>6;
    load_chunk(0, 0);
    if (nch > 1) load_chunk(1, 1);
    for (int c=0;c<nch;c++){
        if (c+1 < nch) cpa_wait1(); else cpa_wait0();
        __syncthreads();
        if (c+2 < nch) load_chunk(c+2, (c+2)%3);
        mma_stage(acc, sb + (c%3)*STG, wm0, wn0, lid);
    }

    #pragma unroll
    for (int mi=0;mi<4;mi++)
        #pragma unroll
        for (int ni=0;ni<4;ni++){
            int nn = n0 + wn0 + ni*8 + 2*(lid&3);
            #pragma unroll
            for (int half=0;half<2;half++){
                int m = i0 + wm0 + mi*16 + (lid>>2) + half*8;
                float v0 = acc.a[mi][ni][2*half+0], v1 = acc.a[mi][ni][2*half+1];
                float o0, o1;
                if (EPI==0){
                    float s0 = v0 + bias[nn], s1 = v1 + bias[nn+1];
                    o0 = s0 / (1.0f + __expf(-s0)); o1 = s1 / (1.0f + __expf(-s1));
                } else {
                    const float* rp = resid + (size_t)m*Nld + nn;
                    o0 = v0 + bias[nn] + rp[0]; o1 = v1 + bias[nn+1] + rp[1];
                }
                *(float2*)(C + (size_t)m*Nld + nn) = make_float2(o0, o1);
            }
        }
}

// ---------------------------------------------------------------------------
// transpose + split v
// ---------------------------------------------------------------------------
__global__ void transsplit_k(const float* __restrict__ V,
                             __nv_bfloat16* __restrict__ Oh, __nv_bfloat16* __restrict__ Ol)
{
    __shared__ float t[32][33];
    int s = blockIdx.z, h = s>>2, b = s&3;
    int j0 = blockIdx.x*32, d0 = blockIdx.y*32;
    int tx = threadIdx.x, ty = threadIdx.y;
    #pragma unroll
    for (int r=0;r<4;r++){
        int j = j0 + ty + r*8;
        t[ty+r*8][tx] = V[((size_t)j*BN_ + b)*D1N + h*HDN + d0 + tx];
    }
    __syncthreads();
    #pragma unroll
    for (int r=0;r<4;r++){
        int d = d0 + ty + r*8;
        float v = t[tx][ty+r*8];
        __nv_bfloat16 hi = __float2bfloat16(v);
        size_t off = ((size_t)s*HDN + d)*LN + j0 + tx;
        Oh[off] = hi;
        Ol[off] = __float2bfloat16(v - __bfloat162float(hi));
    }
}

// ---------------------------------------------------------------------------
// Pipelined toeplitz GEMM: A from precomputed tiles, B from vth/vtl.
// Tile 128(l) x 128(d), K-chunk 64 over j, 32 chunks, 3-stage pipeline.
// ---------------------------------------------------------------------------
__global__ void __launch_bounds__(256)
toep_k(const __nv_bfloat16* __restrict__ Vh_, const __nv_bfloat16* __restrict__ Vl_,
       const float* __restrict__ U,
       __nv_bfloat16* __restrict__ Aoh, __nv_bfloat16* __restrict__ Aol)
{
    extern __shared__ char smem[];
    const uint32_t sb = smem_u32(smem);
    int tid = threadIdx.x, wid = tid>>5, lid = tid&31;
    int s = blockIdx.z, h = s>>2, b = s&3;
    int i0 = blockIdx.y*128;
    int d0 = blockIdx.x*128;
    int wm0 = (wid>>2)*64, wn0 = (wid&3)*32;
    const __nv_bfloat16* vh = Vh_ + (size_t)s*HDN*LN + (size_t)d0*LN;
    const __nv_bfloat16* vl = Vl_ + (size_t)s*HDN*LN + (size_t)d0*LN;
    Acc acc;
    #pragma unroll
    for (int i=0;i<4;i++)
        #pragma unroll
        for (int j=0;j<4;j++)
            #pragma unroll
            for (int r=0;r<4;r++) acc.a[i][j][r] = 0.f;

    int lr = tid>>3, lq = tid&7;
    uint32_t soT = SWZ(lr*128 + lq*16);
    int tibase = (blockIdx.y<<1) + 31;        // ti = 2*by + 31 - c

    auto load_chunk = [&](int c, int st){
        uint32_t bs = sb + st*STG;
        int j0 = c<<6;
        size_t tb = ((size_t)h*62 + (tibase - c))*8192;
        const char* th = (const char*)g_tth + tb*2;
        const char* tl = (const char*)g_ttl + tb*2;
        #pragma unroll
        for (int it=0;it<4;it++){
            uint32_t lin = (uint32_t)(it*256+tid)*16;     // verbatim 16KB tile copy
            cpa16(bs+TA_H+lin, th+lin);
            cpa16(bs+TA_L+lin, tl+lin);
            int r = lr + it*32;
            uint32_t so = soT + it*(32*128);
            size_t go = (size_t)r*LN + j0 + lq*8;
            cpa16(bs+TB_H+so, vh+go);
            cpa16(bs+TB_L+so, vl+go);
        }
        cpa_commit();
    };

    load_chunk(0, 0);
    load_chunk(1, 1);
    for (int c=0;c<32;c++){
        if (c+1 < 32) cpa_wait1(); else cpa_wait0();
        __syncthreads();
        if (c+2 < 32) load_chunk(c+2, (c+2)%3);
        mma_stage(acc, sb + (c%3)*STG, wm0, wn0, lid);
    }

    #pragma unroll
    for (int mi=0;mi<4;mi++)
        #pragma unroll
        for (int ni=0;ni<4;ni++){
            int d = d0 + wn0 + ni*8 + 2*(lid&3);
            #pragma unroll
            for (int half=0;half<2;half++){
                int m = i0 + wm0 + mi*16 + (lid>>2) + half*8;
                size_t off = ((size_t)m*BN_ + b)*D1N + h*HDN + d;
                float a0 = acc.a[mi][ni][2*half+0] * U[off];
                float a1 = acc.a[mi][ni][2*half+1] * U[off+1];
                __nv_bfloat16 h0 = __float2bfloat16(a0), h1 = __float2bfloat16(a1);
                *(uint32_t*)(Aoh + off) =
                    (uint32_t)__bfloat16_as_ushort(h0) | ((uint32_t)__bfloat16_as_ushort(h1)<<16);
                *(uint32_t*)(Aol + off) = pk(a0-__bfloat162float(h0), a1-__bfloat162float(h1));
            }
        }
}

// ---------------------------------------------------------------------------
extern "C" void kernel_launch(void* const* d_in, const int* in_sizes, int n_in,
                              void* d_out, int out_size)
{
    const float* q   = (const float*)d_in[0];
    const float* u_w = (const float*)d_in[3];
    const float* u_b = (const float*)d_in[4];
    const float* v_w = (const float*)d_in[5];
    const float* v_b = (const float*)d_in[6];
    const float* o_w = (const float*)d_in[7];
    const float* o_b = (const float*)d_in[8];
    const float* pos = (const float*)d_in[9];
    const float* zer = (const float*)d_in[10];
    const float* neg = (const float*)d_in[11];
    float* out = (float*)d_out;

    cudaFuncSetAttribute(gemm_k<0>, cudaFuncAttributeMaxDynamicSharedMemorySize, SMEM_SZ);
    cudaFuncSetAttribute(gemm_k<1>, cudaFuncAttributeMaxDynamicSharedMemorySize, SMEM_SZ);
    cudaFuncSetAttribute(toep_k,    cudaFuncAttributeMaxDynamicSharedMemorySize, SMEM_SZ);

    void *p;
    #define SYM(v, sym) cudaGetSymbolAddress(&p, sym); auto* v = (decltype(&sym[0]))p;
    SYM(xh,  g_xh);  SYM(xl,  g_xl);
    SYM(uwh, g_uwh); SYM(uwl, g_uwl);
    SYM(vwh, g_vwh); SYM(vwl, g_vwl);
    SYM(owh, g_owh); SYM(owl, g_owl);
    SYM(ug,  g_u);   SYM(vg,  g_v);
    SYM(vth, g_vth); SYM(vtl, g_vtl);
    SYM(ah,  g_ah);  SYM(al,  g_al);
    #undef SYM

    rmsnorm_k<<<MN, 256>>>(q, xh, xl);
    split_k<<<(D1N*EN/4+255)/256, 256>>>(u_w, uwh, uwl, D1N*EN/4);
    split_k<<<(D1N*EN/4+255)/256, 256>>>(v_w, vwh, vwl, D1N*EN/4);
    split_k<<<(EN*D1N/4+255)/256, 256>>>(o_w, owh, owl, EN*D1N/4);
    build_t_k<<<dim3(LN/256, HN), 256>>>(pos, zer, neg);
    toeptiles_k<<<dim3(62, HN), 256>>>();
    gemm_k<0><<<dim3(D1N/128, MN/128), 256, SMEM_SZ>>>(xh, xl, uwh, uwl, u_b, nullptr, ug, EN, D1N);
    gemm_k<0><<<dim3(D1N/128, MN/128), 256, SMEM_SZ>>>(xh, xl, vwh, vwl, v_b, nullptr, vg, EN, D1N);
    transsplit_k<<<dim3(LN/32, HDN/32, 32), dim3(32,8)>>>(vg, vth, vtl);
    toep_k<<<dim3(HDN/128, LN/128, 32), 256, SMEM_SZ>>>(vth, vtl, ug, ah, al);
    gemm_k<1><<<dim3(EN/128, MN/128), 256, SMEM_SZ>>>(ah, al, owh, owl, o_b, q, out, D1N, EN);
}

// round 7
// speedup vs baseline: 2.7837x; 2.4803x over previous
#include <cuda_runtime.h>
#include <cuda_fp16.h>
#include <cstdint>
#include <math.h>

#define LN   2048
#define BN_  4
#define EN   1024
#define HN   8
#define D1N  2048
#define HDN  256
#define MN   (LN*BN_)   // 8192

// ---------------- device scratch ----------------
__device__ __align__(16) __half g_x[MN*EN];
__device__ __align__(16) __half g_uw[D1N*EN], g_vw[D1N*EN], g_ow[EN*D1N];
__device__ __align__(16) float  g_u[MN*D1N], g_v[MN*D1N];
__device__ __align__(16) __half g_vt[(size_t)32*HDN*LN];
__device__ __align__(16) __half g_a[MN*D1N];
__device__ __align__(16) float  g_t[HN*4096];
// precomputed toeplitz A tiles: 8 heads x 62 deltas x (128x64) f16, pre-swizzled
__device__ __align__(16) __half g_tt[(size_t)HN*62*8192];

// ---------------- helpers ----------------
__device__ __forceinline__ uint32_t smem_u32(const void* p){
    uint32_t a;
    asm("{ .reg .u64 t; cvta.to.shared.u64 t, %1; cvt.u32.u64 %0, t; }" : "=r"(a) : "l"(p));
    return a;
}
#define SWZ(o) ((uint32_t)(o) ^ ((((uint32_t)(o))>>3)&0x70))

__device__ __forceinline__ uint32_t pkh(float a, float b){
    __half2 h = __floats2half2_rn(a, b);
    return *reinterpret_cast<uint32_t*>(&h);
}
__device__ __forceinline__ void ldsm4(uint32_t* r, uint32_t addr){
    asm volatile("ldmatrix.sync.aligned.m8n8.x4.shared.b16 {%0,%1,%2,%3}, [%4];"
                 : "=r"(r[0]),"=r"(r[1]),"=r"(r[2]),"=r"(r[3]) : "r"(addr));
}
__device__ __forceinline__ void ldsm2(uint32_t* r, uint32_t addr){
    asm volatile("ldmatrix.sync.aligned.m8n8.x2.shared.b16 {%0,%1}, [%2];"
                 : "=r"(r[0]),"=r"(r[1]) : "r"(addr));
}
__device__ __forceinline__ void mma16816(float* d, const uint32_t* a, const uint32_t* b){
    asm volatile("mma.sync.aligned.m16n8k16.row.col.f32.f16.f16.f32 "
        "{%0,%1,%2,%3}, {%4,%5,%6,%7}, {%8,%9}, {%0,%1,%2,%3};"
        : "+f"(d[0]),"+f"(d[1]),"+f"(d[2]),"+f"(d[3])
        : "r"(a[0]),"r"(a[1]),"r"(a[2]),"r"(a[3]), "r"(b[0]),"r"(b[1]));
}
__device__ __forceinline__ void cpa16(uint32_t s, const void* g){
    asm volatile("cp.async.cg.shared.global [%0], [%1], 16;" :: "r"(s), "l"(g));
}
__device__ __forceinline__ void cpa_commit(){ asm volatile("cp.async.commit_group;" ::: "memory"); }
__device__ __forceinline__ void cpa_wait0(){ asm volatile("cp.async.wait_group 0;" ::: "memory"); }
__device__ __forceinline__ void cpa_wait1(){ asm volatile("cp.async.wait_group 1;" ::: "memory"); }

// SMEM per stage: A 16K | B 16K (128x64 f16 each); 3 stages
#define TA_  0
#define TB_  16384
#define STG  32768
#define SMEM_SZ (3*STG)   // 98304

// ---------------------------------------------------------------------------
__global__ void rmsnorm_k(const float* __restrict__ q, __half* __restrict__ x)
{
    int m = blockIdx.x, t = threadIdx.x;
    float4 a = reinterpret_cast<const float4*>(q + (size_t)m*EN)[t];
    float ss = a.x*a.x + a.y*a.y + a.z*a.z + a.w*a.w;
    #pragma unroll
    for (int o=16;o;o>>=1) ss += __shfl_xor_sync(0xffffffffu, ss, o);
    __shared__ float sred[8];
    if ((t&31)==0) sred[t>>5] = ss;
    __syncthreads();
    if (t<8){
        float v = sred[t];
        #pragma unroll
        for (int o=4;o;o>>=1) v += __shfl_xor_sync(0xffu, v, o);
        if (t==0) sred[0] = v;
    }
    __syncthreads();
    float inv = 1.0f / (sqrtf(sred[0]*(1.0f/EN)) + 1e-8f);
    uint2 w = make_uint2(pkh(a.x*inv, a.y*inv), pkh(a.z*inv, a.w*inv));
    *reinterpret_cast<uint2*>(x + (size_t)m*EN + t*4) = w;
}

__global__ void cvt_k(const float* __restrict__ w, __half* __restrict__ o, int n4)
{
    int i = blockIdx.x*256 + threadIdx.x;
    if (i >= n4) return;
    float4 a = reinterpret_cast<const float4*>(w)[i];
    reinterpret_cast<uint2*>(o)[i] = make_uint2(pkh(a.x,a.y), pkh(a.z,a.w));
}

__global__ void build_t_k(const float* __restrict__ pos, const float* __restrict__ zero,
                          const float* __restrict__ neg)
{
    int h = blockIdx.y;
    int k = blockIdx.x*256 + threadIdx.x;
    if (k >= LN) return;
    int base = h*4096;
    if (k==0){ g_t[base+2047] = zero[h]; g_t[base+4095] = 0.f; }
    else {
        g_t[base+2047+k] = pos[h*(LN-1)+k-1];
        g_t[base+2047-k] = neg[h*(LN-1)+k-1];
    }
}

// ---------------------------------------------------------------------------
// Precompute toeplitz A tiles (128x64 f16, SW128-swizzled)
// ---------------------------------------------------------------------------
__global__ void toeptiles_k()
{
    __shared__ float sT[192];
    int ti = blockIdx.x, h = blockIdx.y, tid = threadIdx.x;
    int gb = h*4096 + 1984 + (ti-31)*64;
    if (tid < 191) sT[tid] = g_t[gb+tid];
    __syncthreads();
    char* dst = (char*)g_tt + (((size_t)h*62 + ti)*8192)*2;
    #pragma unroll
    for (int it=0;it<4;it++){
        int idx = it*256+tid, m = idx>>3, k8 = (idx&7)<<3;
        int base = m + 63 - k8;
        uint32_t so = SWZ(m*128 + k8*2);
        uint32_t w0 = pkh(sT[base],   sT[base-1]);
        uint32_t w1 = pkh(sT[base-2], sT[base-3]);
        uint32_t w2 = pkh(sT[base-4], sT[base-5]);
        uint32_t w3 = pkh(sT[base-6], sT[base-7]);
        *(uint4*)(dst+so) = make_uint4(w0,w1,w2,w3);
    }
}

// ---------------------------------------------------------------------------
// MMA core: 128x128 tile, single fp16 segment.
// ---------------------------------------------------------------------------
struct Acc { float a[4][4][4]; };

__device__ __forceinline__ void mma_stage(Acc& A, uint32_t base, int wm0, int wn0, int lid)
{
    #pragma unroll
    for (int ks=0;ks<4;ks++){
        uint32_t af[4][4], bf_[4][2];
        int arow = ((lid>>3)&1)*8 + (lid&7);
        int acol = ks*16 + ((lid>>4)&1)*8;
        #pragma unroll
        for (int mi=0;mi<4;mi++)
            ldsm4(af[mi], base+TA_+SWZ((wm0+mi*16+arow)*128 + acol*2));
        int l2 = lid&15;
        int brow = l2&7;
        int bcol = ks*16 + ((l2>>3)&1)*8;
        #pragma unroll
        for (int ni=0;ni<4;ni++)
            ldsm2(bf_[ni], base+TB_+SWZ((wn0+ni*8+brow)*128 + bcol*2));
        #pragma unroll
        for (int mi=0;mi<4;mi++)
            #pragma unroll
            for (int ni=0;ni<4;ni++)
                mma16816(A.a[mi][ni], af[mi], bf_[ni]);
    }
}

// ---------------------------------------------------------------------------
// Pipelined fp16 GEMM, tile 128x128, K-chunk 64, 3-stage cp.async.
// EPI 0: silu(acc+bias) -> f32. EPI 1: acc+bias+resid -> f32.
// ---------------------------------------------------------------------------
template<int EPI>
__global__ void __launch_bounds__(256, 2)
gemm_k(const __half* __restrict__ Ah, const __half* __restrict__ Bh,
       const float* __restrict__ bias, const float* __restrict__ resid,
       float* __restrict__ C, int K, int Nld)
{
    extern __shared__ char smem[];
    const uint32_t sb = smem_u32(smem);
    int tid = threadIdx.x, wid = tid>>5, lid = tid&31;
    int i0 = blockIdx.y*128, n0 = blockIdx.x*128;
    int wm0 = (wid>>2)*64, wn0 = (wid&3)*32;
    Acc acc;
    #pragma unroll
    for (int i=0;i<4;i++)
        #pragma unroll
        for (int j=0;j<4;j++)
            #pragma unroll
            for (int r=0;r<4;r++) acc.a[i][j][r] = 0.f;

    int lr = tid>>3, lq = tid&7;
    uint32_t soT = SWZ(lr*128 + lq*16);

    auto load_chunk = [&](int c, int st){
        uint32_t bs = sb + st*STG;
        int kt = c<<6;
        #pragma unroll
        for (int it=0;it<4;it++){
            int r = lr + it*32;
            uint32_t so = soT + it*(32*128);
            cpa16(bs+TA_+so, Ah + (size_t)(i0 + r)*K + kt + lq*8);
            cpa16(bs+TB_+so, Bh + (size_t)(n0 + r)*K + kt + lq*8);
        }
        cpa_commit();
    };

    const int nch = K>>6;
    load_chunk(0, 0);
    if (nch > 1) load_chunk(1, 1);
    for (int c=0;c<nch;c++){
        if (c+1 < nch) cpa_wait1(); else cpa_wait0();
        __syncthreads();
        if (c+2 < nch) load_chunk(c+2, (c+2)%3);
        mma_stage(acc, sb + (c%3)*STG, wm0, wn0, lid);
    }

    #pragma unroll
    for (int mi=0;mi<4;mi++)
        #pragma unroll
        for (int ni=0;ni<4;ni++){
            int nn = n0 + wn0 + ni*8 + 2*(lid&3);
            #pragma unroll
            for (int half_=0;half_<2;half_++){
                int m = i0 + wm0 + mi*16 + (lid>>2) + half_*8;
                float v0 = acc.a[mi][ni][2*half_+0], v1 = acc.a[mi][ni][2*half_+1];
                float o0, o1;
                if (EPI==0){
                    float s0 = v0 + bias[nn], s1 = v1 + bias[nn+1];
                    o0 = s0 / (1.0f + __expf(-s0)); o1 = s1 / (1.0f + __expf(-s1));
                } else {
                    const float* rp = resid + (size_t)m*Nld + nn;
                    o0 = v0 + bias[nn] + rp[0]; o1 = v1 + bias[nn+1] + rp[1];
                }
                *(float2*)(C + (size_t)m*Nld + nn) = make_float2(o0, o1);
            }
        }
}

// ---------------------------------------------------------------------------
// transpose + convert v: (l,b,h*256+d) f32 -> vt[(h*4+b)*256+d][l] f16
// ---------------------------------------------------------------------------
__global__ void transsplit_k(const float* __restrict__ V, __half* __restrict__ O)
{
    __shared__ float t[32][33];
    int s = blockIdx.z, h = s>>2, b = s&3;
    int j0 = blockIdx.x*32, d0 = blockIdx.y*32;
    int tx = threadIdx.x, ty = threadIdx.y;
    #pragma unroll
    for (int r=0;r<4;r++){
        int j = j0 + ty + r*8;
        t[ty+r*8][tx] = V[((size_t)j*BN_ + b)*D1N + h*HDN + d0 + tx];
    }
    __syncthreads();
    #pragma unroll
    for (int r=0;r<4;r++){
        int d = d0 + ty + r*8;
        O[((size_t)s*HDN + d)*LN + j0 + tx] = __float2half(t[tx][ty+r*8]);
    }
}

// ---------------------------------------------------------------------------
// Pipelined toeplitz GEMM: A from precomputed f16 tiles, B from vt.
// Tile 128(l) x 128(d), K-chunk 64 over j, 32 chunks, fused gating epilogue.
// ---------------------------------------------------------------------------
__global__ void __launch_bounds__(256, 2)
toep_k(const __half* __restrict__ Vt, const float* __restrict__ U,
       __half* __restrict__ Ao)
{
    extern __shared__ char smem[];
    const uint32_t sb = smem_u32(smem);
    int tid = threadIdx.x, wid = tid>>5, lid = tid&31;
    int s = blockIdx.z, h = s>>2, b = s&3;
    int i0 = blockIdx.y*128;
    int d0 = blockIdx.x*128;
    int wm0 = (wid>>2)*64, wn0 = (wid&3)*32;
    const __half* vt = Vt + (size_t)s*HDN*LN + (size_t)d0*LN;
    Acc acc;
    #pragma unroll
    for (int i=0;i<4;i++)
        #pragma unroll
        for (int j=0;j<4;j++)
            #pragma unroll
            for (int r=0;r<4;r++) acc.a[i][j][r] = 0.f;

    int lr = tid>>3, lq = tid&7;
    uint32_t soT = SWZ(lr*128 + lq*16);
    int tibase = (blockIdx.y<<1) + 31;

    auto load_chunk = [&](int c, int st){
        uint32_t bs = sb + st*STG;
        int j0 = c<<6;
        const char* th = (const char*)g_tt + (((size_t)h*62 + (tibase - c))*8192)*2;
        #pragma unroll
        for (int it=0;it<4;it++){
            uint32_t lin = (uint32_t)(it*256+tid)*16;   // verbatim 16KB tile copy
            cpa16(bs+TA_+lin, th+lin);
            int r = lr + it*32;
            uint32_t so = soT + it*(32*128);
            cpa16(bs+TB_+so, vt + (size_t)r*LN + j0 + lq*8);
        }
        cpa_commit();
    };

    load_chunk(0, 0);
    load_chunk(1, 1);
    for (int c=0;c<32;c++){
        if (c+1 < 32) cpa_wait1(); else cpa_wait0();
        __syncthreads();
        if (c+2 < 32) load_chunk(c+2, (c+2)%3);
        mma_stage(acc, sb + (c%3)*STG, wm0, wn0, lid);
    }

    #pragma unroll
    for (int mi=0;mi<4;mi++)
        #pragma unroll
        for (int ni=0;ni<4;ni++){
            int d = d0 + wn0 + ni*8 + 2*(lid&3);
            #pragma unroll
            for (int half_=0;half_<2;half_++){
                int m = i0 + wm0 + mi*16 + (lid>>2) + half_*8;
                size_t off = ((size_t)m*BN_ + b)*D1N + h*HDN + d;
                float a0 = acc.a[mi][ni][2*half_+0] * U[off];
                float a1 = acc.a[mi][ni][2*half_+1] * U[off+1];
                *(uint32_t*)(Ao + off) = pkh(a0, a1);
            }
        }
}

// ---------------------------------------------------------------------------
extern "C" void kernel_launch(void* const* d_in, const int* in_sizes, int n_in,
                              void* d_out, int out_size)
{
    const float* q   = (const float*)d_in[0];
    const float* u_w = (const float*)d_in[3];
    const float* u_b = (const float*)d_in[4];
    const float* v_w = (const float*)d_in[5];
    const float* v_b = (const float*)d_in[6];
    const float* o_w = (const float*)d_in[7];
    const float* o_b = (const float*)d_in[8];
    const float* pos = (const float*)d_in[9];
    const float* zer = (const float*)d_in[10];
    const float* neg = (const float*)d_in[11];
    float* out = (float*)d_out;

    cudaFuncSetAttribute(gemm_k<0>, cudaFuncAttributeMaxDynamicSharedMemorySize, SMEM_SZ);
    cudaFuncSetAttribute(gemm_k<1>, cudaFuncAttributeMaxDynamicSharedMemorySize, SMEM_SZ);
    cudaFuncSetAttribute(toep_k,    cudaFuncAttributeMaxDynamicSharedMemorySize, SMEM_SZ);

    void *p;
    #define SYM(v, sym) cudaGetSymbolAddress(&p, sym); auto* v = (decltype(&sym[0]))p;
    SYM(xg,  g_x);
    SYM(uw,  g_uw); SYM(vw,  g_vw); SYM(ow,  g_ow);
    SYM(ug,  g_u);  SYM(vg,  g_v);
    SYM(vt,  g_vt); SYM(ag,  g_a);
    #undef SYM

    rmsnorm_k<<<MN, 256>>>(q, xg);
    cvt_k<<<(D1N*EN/4+255)/256, 256>>>(u_w, uw, D1N*EN/4);
    cvt_k<<<(D1N*EN/4+255)/256, 256>>>(v_w, vw, D1N*EN/4);
    cvt_k<<<(EN*D1N/4+255)/256, 256>>>(o_w, ow, EN*D1N/4);
    build_t_k<<<dim3(LN/256, HN), 256>>>(pos, zer, neg);
    toeptiles_k<<<dim3(62, HN), 256>>>();
    gemm_k<0><<<dim3(D1N/128, MN/128), 256, SMEM_SZ>>>(xg, uw, u_b, nullptr, ug, EN, D1N);
    gemm_k<0><<<dim3(D1N/128, MN/128), 256, SMEM_SZ>>>(xg, vw, v_b, nullptr, vg, EN, D1N);
    transsplit_k<<<dim3(LN/32, HDN/32, 32), dim3(32,8)>>>(vg, vt);
    toep_k<<<dim3(HDN/128, LN/128, 32), 256, SMEM_SZ>>>(vt, ug, ag);
    gemm_k<1><<<dim3(EN/128, MN/128), 256, SMEM_SZ>>>(ag, ow, o_b, q, out, D1N, EN);
}